// round 14
// baseline (speedup 1.0000x reference)
#include <cuda_runtime.h>
#include <cuda_fp16.h>
#include <cstdint>

// Problem constants
#define Bn   16
#define Nn   4096
#define Mn   1024
#define C1n  128
#define C2n  256
#define CINn 384
#define H1n  256
#define H2n  128

#define WSCALE 0.00048828125f   // 2^-11: keeps inv-dist weights < fp16 max; cancels in ratio

// ---------------- helpers ----------------
__device__ __forceinline__ uint32_t smem_u32(const void* p) {
    uint32_t a;
    asm("{ .reg .u64 t; cvta.to.shared.u64 t, %1; cvt.u32.u64 %0, t; }" : "=r"(a) : "l"(p));
    return a;
}
__device__ __forceinline__ void ldsm4(uint32_t* r, uint32_t addr) {
    asm volatile("ldmatrix.sync.aligned.m8n8.x4.shared.b16 {%0,%1,%2,%3}, [%4];"
        : "=r"(r[0]), "=r"(r[1]), "=r"(r[2]), "=r"(r[3]) : "r"(addr));
}
__device__ __forceinline__ void ldsm4t(uint32_t* r, uint32_t addr) {
    asm volatile("ldmatrix.sync.aligned.m8n8.x4.trans.shared.b16 {%0,%1,%2,%3}, [%4];"
        : "=r"(r[0]), "=r"(r[1]), "=r"(r[2]), "=r"(r[3]) : "r"(addr));
}
__device__ __forceinline__ void mma_f16(float* d, const uint32_t* a, const uint32_t* b) {
    asm volatile("mma.sync.aligned.m16n8k16.row.col.f32.f16.f16.f32 "
        "{%0,%1,%2,%3}, {%4,%5,%6,%7}, {%8,%9}, {%0,%1,%2,%3};"
        : "+f"(d[0]), "+f"(d[1]), "+f"(d[2]), "+f"(d[3])
        : "r"(a[0]), "r"(a[1]), "r"(a[2]), "r"(a[3]), "r"(b[0]), "r"(b[1]));
}
__device__ __forceinline__ uint32_t h2pack(float a, float b) {
    __half2 h = __floats2half2_rn(a, b);
    return *(uint32_t*)&h;
}
// pack + accumulate the QUANTIZED values (keeps num/den weight errors correlated)
__device__ __forceinline__ uint32_t h2pack_acc(float a, float b, float& s) {
    __half2 h = __floats2half2_rn(a, b);
    float2 f = __half22float2(h);
    s += f.x + f.y;
    return *(uint32_t*)&h;
}
#define CP16(dst, src) asm volatile("cp.async.cg.shared.global [%0], [%1], 16;" :: "r"(dst), "l"(src))
#define CPCOMMIT()     asm volatile("cp.async.commit_group;" ::: "memory")
#define CPWAIT(n)      asm volatile("cp.async.wait_group %0;" :: "n"(n) : "memory")

// device scratch (fp16 as u16)
__device__ uint16_t g_p2f[(size_t)Bn * C2n * Mn];
__device__ uint16_t g_p1f[(size_t)Bn * C1n * Nn];
__device__ uint16_t g_w1f[H1n * CINn];
__device__ uint16_t g_w2f[H2n * H1n];

// prep: fp32 -> fp16
__global__ void tofp16(const float* __restrict__ src, uint16_t* __restrict__ dst)
{
    const size_t i = (size_t)blockIdx.x * 256 + threadIdx.x;   // float4 index
    const float4 v = ((const float4*)src)[i];
    uint2 o;
    o.x = h2pack(v.x, v.y);
    o.y = h2pack(v.z, v.w);
    ((uint2*)dst)[i] = o;
}

// paired-row address: two logical 64B rows per 144B physical row (conflict-free ldsm)
#define PR(r) (((r) >> 1) * 144 + ((r) & 1) * 64)

// ================= Fused kernel: interp (fp16 mma) + 2-layer MLP =================
// SMEM map (bytes):
//   [0, 55296)           x tile [384 rows][144]  (fp16, resident both phases)
//   [55296, 114688)      workspace WS:
//     interp: IA 2x5120, IB 2x18432 (-> +47104), xyz SoA 12288 (-> +59392)
//             s_ds/s_den overlay IA(0) after the loop
//     mlp:    MW 2x18432 (h overlays), MW2 2x9216 (-> +55296),
//             b1/b2 overlay the xyz region
#define XOFF  0
#define WS    55296
#define IA(buf)   (WS + (buf) * 5120)
#define IB(buf)   (WS + 10240 + (buf) * 18432)
#define IX2       (WS + 47104)
#define MW(buf)   (WS + (buf) * 18432)
#define MH        (WS)
#define MW2(buf)  (WS + 36864 + (buf) * 9216)
#define B1OFF     (WS + 55296)
#define B2OFF     (WS + 56320)
#define ISMB      114688

__global__ __launch_bounds__(256, 2)
void fp_fused(const float* __restrict__ xyz1,
              const float* __restrict__ xyz2,
              const float* __restrict__ b1,
              const float* __restrict__ b2,
              float* __restrict__ out)
{
    extern __shared__ char smc[];
    const uint32_t sb = smem_u32(smc);
    float* s_x2x = (float*)(smc + IX2);
    float* s_x2y = s_x2x + Mn;
    float* s_x2z = s_x2x + 2 * Mn;
    float* s_ds  = (float*)(smc + WS);          // overlays IA(0), used post-loop
    float* s_den = (float*)(smc + WS + 1024);
    float* s_b1  = (float*)(smc + B1OFF);
    float* s_b2  = (float*)(smc + B2OFF);

    const int tid = threadIdx.x, w = tid >> 5, lane = tid & 31;
    const int b = blockIdx.y, n0 = blockIdx.x * 64;

    // xyz2 -> SoA smem
    for (int m = tid; m < Mn; m += 256) {
        const float3 v = ((const float3*)(xyz2 + (size_t)b * Mn * 3))[m];
        s_x2x[m] = v.x; s_x2y[m] = v.y; s_x2z[m] = v.z;
    }

    // x rows 0..127 from prequantized p1 (overlaps entire interp phase)
    #pragma unroll
    for (int it = 0; it < 4; it++) {
        const int u = tid + it * 256;           // 0..1023
        const int row = u >> 3, s = u & 7;
        CP16(sb + XOFF + row * 144 + s * 16,
             g_p1f + ((size_t)b * C1n + row) * Nn + n0 + s * 8);
    }
    __syncthreads();   // xyz visible

    const int nf = tid & 63;
    const int g  = tid >> 6;
    const float px = xyz1[((size_t)b * Nn + n0 + nf) * 3 + 0];
    const float py = xyz1[((size_t)b * Nn + n0 + nf) * 3 + 1];
    const float pz = xyz1[((size_t)b * Nn + n0 + nf) * 3 + 2];
    float dsum = 0.f;

    const int mw = w & 1, cw = w >> 1;   // interp warp tile: 32 n x 64 c
    float acc[16][4];
    #pragma unroll
    for (int i = 0; i < 16; i++)
        #pragma unroll
        for (int j = 0; j < 4; j++) acc[i][j] = 0.f;

    const size_t p2base = (size_t)b * C2n * Mn;

    #define FILLA(ch) do {                                                         \
        const int _buf = (ch) & 1, _mb = (ch) * 32 + g * 8;                        \
        const float4 xa = *(const float4*)&s_x2x[_mb];                             \
        const float4 xbv = *(const float4*)&s_x2x[_mb + 4];                        \
        const float4 ya = *(const float4*)&s_x2y[_mb];                             \
        const float4 yb = *(const float4*)&s_x2y[_mb + 4];                         \
        const float4 za = *(const float4*)&s_x2z[_mb];                             \
        const float4 zb = *(const float4*)&s_x2z[_mb + 4];                         \
        const float xs[8] = {xa.x, xa.y, xa.z, xa.w, xbv.x, xbv.y, xbv.z, xbv.w};  \
        const float ys[8] = {ya.x, ya.y, ya.z, ya.w, yb.x, yb.y, yb.z, yb.w};      \
        const float zs[8] = {za.x, za.y, za.z, za.w, zb.x, zb.y, zb.z, zb.w};      \
        float iv[8];                                                               \
        _Pragma("unroll")                                                          \
        for (int t = 0; t < 8; t++) {                                              \
            const float dx = px - xs[t];                                           \
            const float dy = py - ys[t];                                           \
            const float dz = pz - zs[t];                                           \
            const float d2 = fmaf(dx, dx, fmaf(dy, dy, fmaf(dz, dz, 1e-16f)));     \
            iv[t] = rsqrtf(d2) * WSCALE;                                           \
        }                                                                          \
        uint4 hv;                                                                  \
        hv.x = h2pack_acc(iv[0], iv[1], dsum);                                     \
        hv.y = h2pack_acc(iv[2], iv[3], dsum);                                     \
        hv.z = h2pack_acc(iv[4], iv[5], dsum);                                     \
        hv.w = h2pack_acc(iv[6], iv[7], dsum);                                     \
        *(uint4*)(smc + IA(_buf) + nf * 80 + g * 16) = hv;                         \
    } while (0)

    #define FILLB(ch) do {                                                         \
        const int _buf = (ch) & 1, _m0 = (ch) * 32;                                \
        _Pragma("unroll")                                                          \
        for (int it = 0; it < 4; it++) {                                           \
            const int u = tid + it * 256;                                          \
            const int c = u >> 2, s = u & 3;                                       \
            CP16(sb + IB(_buf) + PR(c) + s * 16,                                   \
                 g_p2f + p2base + (size_t)c * Mn + _m0 + s * 8);                   \
        }                                                                          \
        CPCOMMIT();                                                                \
    } while (0)

    FILLA(0);
    FILLB(0);   // commit group also covers the p1 cp.asyncs

    for (int ch = 0; ch < 32; ch++) {
        const int buf = ch & 1;
        CPWAIT(0);
        __syncthreads();
        if (ch < 31) { FILLB(ch + 1); FILLA(ch + 1); }

        #pragma unroll
        for (int kk = 0; kk < 2; kk++) {
            uint32_t ah[2][4];
            #pragma unroll
            for (int mt = 0; mt < 2; mt++) {
                const uint32_t row = mw * 32 + mt * 16 + (lane & 15);
                const uint32_t off = row * 80 + kk * 32 + (lane >> 4) * 16;
                ldsm4(ah[mt], sb + IA(buf) + off);
            }
            #pragma unroll
            for (int cp = 0; cp < 4; cp++) {
                const uint32_t c = cw * 64 + cp * 16 + (lane >> 4) * 8 + (lane & 7);
                const uint32_t off = PR(c) + kk * 32 + ((lane >> 3) & 1) * 16;
                uint32_t rh[4];
                ldsm4(rh, sb + IB(buf) + off);
                #pragma unroll
                for (int mt = 0; mt < 2; mt++) {
                    mma_f16(acc[mt * 8 + cp * 2],     ah[mt], rh);
                    mma_f16(acc[mt * 8 + cp * 2 + 1], ah[mt], rh + 2);
                }
            }
        }
    }
    #undef FILLA
    #undef FILLB

    // denominator (quantized-consistent, scaled)
    __syncthreads();
    s_ds[tid] = dsum;
    if (tid < 64) {
        s_b1[tid] = b1[tid]; s_b1[tid + 64] = b1[tid + 64];
        s_b1[tid + 128] = b1[tid + 128]; s_b1[tid + 192] = b1[tid + 192];
        s_b2[tid] = b2[tid]; s_b2[tid + 64] = b2[tid + 64];
    }
    __syncthreads();
    if (tid < 64)
        s_den[tid] = 1.0f / (s_ds[tid] + s_ds[tid + 64] + s_ds[tid + 128] + s_ds[tid + 192]);
    __syncthreads();

    // interp epilogue: write x rows 128..383 as fp16 (direct into resident x-tile)
    #pragma unroll
    for (int mt = 0; mt < 2; mt++) {
        const int nl = mw * 32 + mt * 16 + (lane >> 2);
        const float i0 = s_den[nl], i1 = s_den[nl + 8];
        #pragma unroll
        for (int ct = 0; ct < 8; ct++) {
            const int c = cw * 64 + ct * 8 + (lane & 3) * 2;
            const float* a = acc[mt * 8 + ct];
            __half* r0 = (__half*)(smc + XOFF + (128 + c) * 144);
            __half* r1 = (__half*)(smc + XOFF + (129 + c) * 144);
            r0[nl]     = __float2half_rn(a[0] * i0);
            r1[nl]     = __float2half_rn(a[1] * i0);
            r0[nl + 8] = __float2half_rn(a[2] * i1);
            r1[nl + 8] = __float2half_rn(a[3] * i1);
        }
    }
    __syncthreads();   // x complete; interp workspace (incl. s_ds/s_den) dead

    // ================= Phase 2: MLP =================
    const int ow = w >> 1, nw = w & 1;   // GEMM1 warp: 64 o x 32 n

    // W1 chunk via cp.async of prequantized fp16: 4 x 16B per thread
    #define FILLW1(kc) do {                                                         \
        const int _buf = (kc) & 1;                                                  \
        _Pragma("unroll")                                                           \
        for (int it = 0; it < 4; it++) {                                            \
            const int u = tid + it * 256;                                           \
            const int o = u >> 2, s = u & 3;                                        \
            CP16(sb + MW(_buf) + PR(o) + s * 16,                                    \
                 g_w1f + (size_t)o * CINn + (kc) * 32 + s * 8);                     \
        }                                                                           \
        CPCOMMIT();                                                                 \
    } while (0)

    // W2 chunk via cp.async: 2 x 16B per thread
    #define FILLW2(kc) do {                                                         \
        const int _buf = (kc) & 1;                                                  \
        _Pragma("unroll")                                                           \
        for (int it = 0; it < 2; it++) {                                            \
            const int u = tid + it * 256;                                           \
            const int o = u >> 2, s = u & 3;                                        \
            CP16(sb + MW2(_buf) + PR(o) + s * 16,                                   \
                 g_w2f + (size_t)o * H1n + (kc) * 32 + s * 8);                      \
        }                                                                           \
        CPCOMMIT();                                                                 \
    } while (0)

    // reuse acc as acc1
    #pragma unroll
    for (int i = 0; i < 16; i++)
        #pragma unroll
        for (int j = 0; j < 4; j++) acc[i][j] = 0.f;

    FILLW1(0);

    for (int kc = 0; kc < 12; kc++) {
        const int buf = kc & 1;
        CPWAIT(0);
        __syncthreads();
        if (kc < 11) FILLW1(kc + 1);    // writes OTHER buffer — safe

        #pragma unroll
        for (int kk = 0; kk < 2; kk++) {
            uint32_t wh[4][4];
            #pragma unroll
            for (int mi = 0; mi < 4; mi++) {
                const uint32_t o = ow * 64 + mi * 16 + (lane & 15);
                const uint32_t off = PR(o) + kk * 32 + (lane >> 4) * 16;
                ldsm4(wh[mi], sb + MW(buf) + off);
            }
            uint32_t xh[4][2];
            #pragma unroll
            for (int np = 0; np < 2; np++) {
                const uint32_t row  = kc * 32 + kk * 16 + ((lane >> 3) & 1) * 8 + (lane & 7);
                const uint32_t colb = (nw * 32 + np * 16) * 2 + (lane >> 4) * 16;
                uint32_t r[4];
                ldsm4t(r, sb + XOFF + row * 144 + colb);
                xh[np * 2][0] = r[0]; xh[np * 2][1] = r[1];
                xh[np * 2 + 1][0] = r[2]; xh[np * 2 + 1][1] = r[3];
            }
            #pragma unroll
            for (int mi = 0; mi < 4; mi++)
                #pragma unroll
                for (int ni = 0; ni < 4; ni++)
                    mma_f16(acc[mi * 4 + ni], wh[mi], xh[ni]);
        }
    }
    #undef FILLW1

    __syncthreads();   // all warps done reading MW before h-epilogue overlays it
    FILLW2(0);

    // GEMM1 epilogue: relu + bias -> h [256 k-rows][64 n] fp16 (overlays MW)
    #pragma unroll
    for (int mi = 0; mi < 4; mi++) {
        const int o = ow * 64 + mi * 16 + (lane >> 2);
        const float bia0 = s_b1[o], bia1 = s_b1[o + 8];
        #pragma unroll
        for (int ni = 0; ni < 4; ni++) {
            const int n = nw * 32 + ni * 8 + (lane & 3) * 2;
            const float* a = acc[mi * 4 + ni];
            const float v0 = fmaxf(a[0] + bia0, 0.f);
            const float v1 = fmaxf(a[1] + bia0, 0.f);
            const float v2 = fmaxf(a[2] + bia1, 0.f);
            const float v3 = fmaxf(a[3] + bia1, 0.f);
            *(uint32_t*)(smc + MH + o * 144 + n * 2)       = h2pack(v0, v1);
            *(uint32_t*)(smc + MH + (o + 8) * 144 + n * 2) = h2pack(v2, v3);
        }
    }

    // GEMM2 (distance-1 double buffer)
    const int ow2 = w >> 1;
    float acc2[8][4];
    #pragma unroll
    for (int i = 0; i < 8; i++)
        #pragma unroll
        for (int j = 0; j < 4; j++) acc2[i][j] = 0.f;

    for (int kc = 0; kc < 8; kc++) {
        const int buf = kc & 1;
        CPWAIT(0);
        __syncthreads();            // first iter: h writes + FILLW2(0) visible
        if (kc < 7) FILLW2(kc + 1); // writes OTHER buffer — safe

        #pragma unroll
        for (int kk = 0; kk < 2; kk++) {
            uint32_t wh[2][4];
            #pragma unroll
            for (int mi = 0; mi < 2; mi++) {
                const uint32_t o = ow2 * 32 + mi * 16 + (lane & 15);
                const uint32_t off = PR(o) + kk * 32 + (lane >> 4) * 16;
                ldsm4(wh[mi], sb + MW2(buf) + off);
            }
            uint32_t hh[4][2];
            #pragma unroll
            for (int np = 0; np < 2; np++) {
                const uint32_t row  = kc * 32 + kk * 16 + ((lane >> 3) & 1) * 8 + (lane & 7);
                const uint32_t colb = (nw * 32 + np * 16) * 2 + (lane >> 4) * 16;
                uint32_t r[4];
                ldsm4t(r, sb + MH + row * 144 + colb);
                hh[np * 2][0] = r[0]; hh[np * 2][1] = r[1];
                hh[np * 2 + 1][0] = r[2]; hh[np * 2 + 1][1] = r[3];
            }
            #pragma unroll
            for (int mi = 0; mi < 2; mi++)
                #pragma unroll
                for (int ni = 0; ni < 4; ni++)
                    mma_f16(acc2[mi * 4 + ni], wh[mi], hh[ni]);
        }
    }
    #undef FILLW2

    // output
    #pragma unroll
    for (int mi = 0; mi < 2; mi++) {
        const int o = ow2 * 32 + mi * 16 + (lane >> 2);
        const float bia0 = s_b2[o], bia1 = s_b2[o + 8];
        #pragma unroll
        for (int ni = 0; ni < 4; ni++) {
            const int n = n0 + nw * 32 + ni * 8 + (lane & 3) * 2;
            const float* a = acc2[mi * 4 + ni];
            float2 v0, v1;
            v0.x = fmaxf(a[0] + bia0, 0.f);
            v0.y = fmaxf(a[1] + bia0, 0.f);
            v1.x = fmaxf(a[2] + bia1, 0.f);
            v1.y = fmaxf(a[3] + bia1, 0.f);
            *(float2*)&out[((size_t)b * H2n + o) * Nn + n]     = v0;
            *(float2*)&out[((size_t)b * H2n + o + 8) * Nn + n] = v1;
        }
    }
}

extern "C" void kernel_launch(void* const* d_in, const int* in_sizes, int n_in,
                              void* d_out, int out_size)
{
    const float* xyz1 = (const float*)d_in[0];
    const float* xyz2 = (const float*)d_in[1];
    const float* p1   = (const float*)d_in[2];
    const float* p2   = (const float*)d_in[3];
    const float* W1   = (const float*)d_in[4];
    const float* b1   = (const float*)d_in[5];
    const float* W2   = (const float*)d_in[6];
    const float* b2   = (const float*)d_in[7];
    float* out = (float*)d_out;

    cudaFuncSetAttribute(fp_fused, cudaFuncAttributeMaxDynamicSharedMemorySize, ISMB);

    uint16_t* p2f; cudaGetSymbolAddress((void**)&p2f, g_p2f);
    uint16_t* p1f; cudaGetSymbolAddress((void**)&p1f, g_p1f);
    uint16_t* w1f; cudaGetSymbolAddress((void**)&w1f, g_w1f);
    uint16_t* w2f; cudaGetSymbolAddress((void**)&w2f, g_w2f);

    tofp16<<<(Bn * C2n * Mn / 4) / 256, 256>>>(p2, p2f);
    tofp16<<<(Bn * C1n * Nn / 4) / 256, 256>>>(p1, p1f);
    tofp16<<<(H1n * CINn / 4) / 256, 256>>>(W1, w1f);
    tofp16<<<(H2n * H1n / 4) / 256, 256>>>(W2, w2f);

    dim3 grid(Nn / 64, Bn);
    fp_fused<<<grid, 256, ISMB>>>(xyz1, xyz2, b1, b2, out);
}

// round 15
// speedup vs baseline: 1.0278x; 1.0278x over previous
#include <cuda_runtime.h>
#include <cuda_fp16.h>
#include <cstdint>

// Problem constants
#define Bn   16
#define Nn   4096
#define Mn   1024
#define C1n  128
#define C2n  256
#define CINn 384
#define H1n  256
#define H2n  128

#define WSCALE 0.00048828125f   // 2^-11: keeps inv-dist weights < fp16 max; cancels in ratio

// ---------------- helpers ----------------
__device__ __forceinline__ uint32_t smem_u32(const void* p) {
    uint32_t a;
    asm("{ .reg .u64 t; cvta.to.shared.u64 t, %1; cvt.u32.u64 %0, t; }" : "=r"(a) : "l"(p));
    return a;
}
__device__ __forceinline__ void ldsm4(uint32_t* r, uint32_t addr) {
    asm volatile("ldmatrix.sync.aligned.m8n8.x4.shared.b16 {%0,%1,%2,%3}, [%4];"
        : "=r"(r[0]), "=r"(r[1]), "=r"(r[2]), "=r"(r[3]) : "r"(addr));
}
__device__ __forceinline__ void ldsm4t(uint32_t* r, uint32_t addr) {
    asm volatile("ldmatrix.sync.aligned.m8n8.x4.trans.shared.b16 {%0,%1,%2,%3}, [%4];"
        : "=r"(r[0]), "=r"(r[1]), "=r"(r[2]), "=r"(r[3]) : "r"(addr));
}
__device__ __forceinline__ void mma_f16(float* d, const uint32_t* a, const uint32_t* b) {
    asm volatile("mma.sync.aligned.m16n8k16.row.col.f32.f16.f16.f32 "
        "{%0,%1,%2,%3}, {%4,%5,%6,%7}, {%8,%9}, {%0,%1,%2,%3};"
        : "+f"(d[0]), "+f"(d[1]), "+f"(d[2]), "+f"(d[3])
        : "r"(a[0]), "r"(a[1]), "r"(a[2]), "r"(a[3]), "r"(b[0]), "r"(b[1]));
}
__device__ __forceinline__ uint32_t h2pack(float a, float b) {
    __half2 h = __floats2half2_rn(a, b);
    return *(uint32_t*)&h;
}
// pack + accumulate the QUANTIZED values (keeps num/den weight errors correlated)
__device__ __forceinline__ uint32_t h2pack_acc(float a, float b, float& s) {
    __half2 h = __floats2half2_rn(a, b);
    float2 f = __half22float2(h);
    s += f.x + f.y;
    return *(uint32_t*)&h;
}
#define CP16(dst, src) asm volatile("cp.async.cg.shared.global [%0], [%1], 16;" :: "r"(dst), "l"(src))
#define CPCOMMIT()     asm volatile("cp.async.commit_group;" ::: "memory")
#define CPWAIT(n)      asm volatile("cp.async.wait_group %0;" :: "n"(n) : "memory")

// device scratch (fp16 as u16)
__device__ uint16_t g_p2f[(size_t)Bn * C2n * Mn];
__device__ uint16_t g_p1f[(size_t)Bn * C1n * Nn];
__device__ uint16_t g_w1f[H1n * CINn];
__device__ uint16_t g_w2f[H2n * H1n];

// ---------------- prep: single launch, all four fp32 -> fp16 conversions ----------------
#define P2E ((size_t)Bn * C2n * Mn / 4)    // 1048576 float4
#define P1E ((size_t)Bn * C1n * Nn / 4)    // 2097152
#define W1E ((size_t)H1n * CINn / 4)       // 24576
#define W2E ((size_t)H2n * H1n / 4)        // 8192
#define PREP_TOT (P2E + P1E + W1E + W2E)   // 3178496
#define PREP_BLKS ((PREP_TOT) / 256)       // 12416

__global__ void prep_all(const float* __restrict__ p2, const float* __restrict__ p1,
                         const float* __restrict__ W1, const float* __restrict__ W2)
{
    const size_t i = (size_t)blockIdx.x * 256 + threadIdx.x;
    const float4* src;
    uint2* dst;
    size_t off;
    if (i < P2E)                    { src = (const float4*)p2; dst = (uint2*)g_p2f; off = i; }
    else if (i < P2E + P1E)         { src = (const float4*)p1; dst = (uint2*)g_p1f; off = i - P2E; }
    else if (i < P2E + P1E + W1E)   { src = (const float4*)W1; dst = (uint2*)g_w1f; off = i - P2E - P1E; }
    else                            { src = (const float4*)W2; dst = (uint2*)g_w2f; off = i - P2E - P1E - W1E; }
    const float4 v = src[off];
    uint2 o;
    o.x = h2pack(v.x, v.y);
    o.y = h2pack(v.z, v.w);
    dst[off] = o;
}

// paired-row address: two logical 64B rows per 144B physical row (conflict-free ldsm)
#define PR(r) (((r) >> 1) * 144 + ((r) & 1) * 64)

// ================= Fused kernel: interp (fp16 mma) + 2-layer MLP =================
// SMEM map (bytes):
//   [0, 55296)           x tile [384 rows][144]  (fp16, resident both phases)
//   [55296, 114688)      workspace WS:
//     interp: IA 2x5120, IB 2x18432 (-> +47104), xyz SoA 12288 (-> +59392)
//             s_ds/s_den overlay IA(0) after the loop
//     mlp:    MW 2x18432 (h overlays), MW2 2x9216 (-> +55296),
//             b1/b2 overlay the xyz region
#define XOFF  0
#define WS    55296
#define IA(buf)   (WS + (buf) * 5120)
#define IB(buf)   (WS + 10240 + (buf) * 18432)
#define IX2       (WS + 47104)
#define MW(buf)   (WS + (buf) * 18432)
#define MH        (WS)
#define MW2(buf)  (WS + 36864 + (buf) * 9216)
#define B1OFF     (WS + 55296)
#define B2OFF     (WS + 56320)
#define ISMB      114688

__global__ __launch_bounds__(256, 2)
void fp_fused(const float* __restrict__ xyz1,
              const float* __restrict__ xyz2,
              const float* __restrict__ b1,
              const float* __restrict__ b2,
              float* __restrict__ out)
{
    extern __shared__ char smc[];
    const uint32_t sb = smem_u32(smc);
    float* s_x2x = (float*)(smc + IX2);
    float* s_x2y = s_x2x + Mn;
    float* s_x2z = s_x2x + 2 * Mn;
    float* s_ds  = (float*)(smc + WS);          // overlays IA(0), used post-loop
    float* s_den = (float*)(smc + WS + 1024);
    float* s_b1  = (float*)(smc + B1OFF);
    float* s_b2  = (float*)(smc + B2OFF);

    const int tid = threadIdx.x, w = tid >> 5, lane = tid & 31;
    const int b = blockIdx.y, n0 = blockIdx.x * 64;

    // xyz2 -> SoA smem
    for (int m = tid; m < Mn; m += 256) {
        const float3 v = ((const float3*)(xyz2 + (size_t)b * Mn * 3))[m];
        s_x2x[m] = v.x; s_x2y[m] = v.y; s_x2z[m] = v.z;
    }

    // x rows 0..127 from prequantized p1 (overlaps entire interp phase)
    #pragma unroll
    for (int it = 0; it < 4; it++) {
        const int u = tid + it * 256;           // 0..1023
        const int row = u >> 3, s = u & 7;
        CP16(sb + XOFF + row * 144 + s * 16,
             g_p1f + ((size_t)b * C1n + row) * Nn + n0 + s * 8);
    }
    __syncthreads();   // xyz visible

    const int nf = tid & 63;
    const int g  = tid >> 6;
    const float px = xyz1[((size_t)b * Nn + n0 + nf) * 3 + 0];
    const float py = xyz1[((size_t)b * Nn + n0 + nf) * 3 + 1];
    const float pz = xyz1[((size_t)b * Nn + n0 + nf) * 3 + 2];
    float dsum = 0.f;

    const int mw = w & 1, cw = w >> 1;   // interp warp tile: 32 n x 64 c
    float acc[16][4];
    #pragma unroll
    for (int i = 0; i < 16; i++)
        #pragma unroll
        for (int j = 0; j < 4; j++) acc[i][j] = 0.f;

    const size_t p2base = (size_t)b * C2n * Mn;

    #define FILLA(ch) do {                                                         \
        const int _buf = (ch) & 1, _mb = (ch) * 32 + g * 8;                        \
        const float4 xa = *(const float4*)&s_x2x[_mb];                             \
        const float4 xbv = *(const float4*)&s_x2x[_mb + 4];                        \
        const float4 ya = *(const float4*)&s_x2y[_mb];                             \
        const float4 yb = *(const float4*)&s_x2y[_mb + 4];                         \
        const float4 za = *(const float4*)&s_x2z[_mb];                             \
        const float4 zb = *(const float4*)&s_x2z[_mb + 4];                         \
        const float xs[8] = {xa.x, xa.y, xa.z, xa.w, xbv.x, xbv.y, xbv.z, xbv.w};  \
        const float ys[8] = {ya.x, ya.y, ya.z, ya.w, yb.x, yb.y, yb.z, yb.w};      \
        const float zs[8] = {za.x, za.y, za.z, za.w, zb.x, zb.y, zb.z, zb.w};      \
        float iv[8];                                                               \
        _Pragma("unroll")                                                          \
        for (int t = 0; t < 8; t++) {                                              \
            const float dx = px - xs[t];                                           \
            const float dy = py - ys[t];                                           \
            const float dz = pz - zs[t];                                           \
            const float d2 = fmaf(dx, dx, fmaf(dy, dy, fmaf(dz, dz, 1e-16f)));     \
            iv[t] = rsqrtf(d2) * WSCALE;                                           \
        }                                                                          \
        uint4 hv;                                                                  \
        hv.x = h2pack_acc(iv[0], iv[1], dsum);                                     \
        hv.y = h2pack_acc(iv[2], iv[3], dsum);                                     \
        hv.z = h2pack_acc(iv[4], iv[5], dsum);                                     \
        hv.w = h2pack_acc(iv[6], iv[7], dsum);                                     \
        *(uint4*)(smc + IA(_buf) + nf * 80 + g * 16) = hv;                         \
    } while (0)

    #define FILLB(ch) do {                                                         \
        const int _buf = (ch) & 1, _m0 = (ch) * 32;                                \
        _Pragma("unroll")                                                          \
        for (int it = 0; it < 4; it++) {                                           \
            const int u = tid + it * 256;                                          \
            const int c = u >> 2, s = u & 3;                                       \
            CP16(sb + IB(_buf) + PR(c) + s * 16,                                   \
                 g_p2f + p2base + (size_t)c * Mn + _m0 + s * 8);                   \
        }                                                                          \
        CPCOMMIT();                                                                \
    } while (0)

    FILLA(0);
    FILLB(0);   // commit group also covers the p1 cp.asyncs

    for (int ch = 0; ch < 32; ch++) {
        const int buf = ch & 1;
        CPWAIT(0);
        __syncthreads();
        if (ch < 31) { FILLB(ch + 1); FILLA(ch + 1); }

        #pragma unroll
        for (int kk = 0; kk < 2; kk++) {
            uint32_t ah[2][4];
            #pragma unroll
            for (int mt = 0; mt < 2; mt++) {
                const uint32_t row = mw * 32 + mt * 16 + (lane & 15);
                const uint32_t off = row * 80 + kk * 32 + (lane >> 4) * 16;
                ldsm4(ah[mt], sb + IA(buf) + off);
            }
            #pragma unroll
            for (int cp = 0; cp < 4; cp++) {
                const uint32_t c = cw * 64 + cp * 16 + (lane >> 4) * 8 + (lane & 7);
                const uint32_t off = PR(c) + kk * 32 + ((lane >> 3) & 1) * 16;
                uint32_t rh[4];
                ldsm4(rh, sb + IB(buf) + off);
                #pragma unroll
                for (int mt = 0; mt < 2; mt++) {
                    mma_f16(acc[mt * 8 + cp * 2],     ah[mt], rh);
                    mma_f16(acc[mt * 8 + cp * 2 + 1], ah[mt], rh + 2);
                }
            }
        }
    }
    #undef FILLA
    #undef FILLB

    // denominator (quantized-consistent, scaled)
    __syncthreads();
    s_ds[tid] = dsum;
    if (tid < 64) {
        s_b1[tid] = b1[tid]; s_b1[tid + 64] = b1[tid + 64];
        s_b1[tid + 128] = b1[tid + 128]; s_b1[tid + 192] = b1[tid + 192];
        s_b2[tid] = b2[tid]; s_b2[tid + 64] = b2[tid + 64];
    }
    __syncthreads();
    if (tid < 64)
        s_den[tid] = 1.0f / (s_ds[tid] + s_ds[tid + 64] + s_ds[tid + 128] + s_ds[tid + 192]);
    __syncthreads();

    // interp epilogue: write x rows 128..383 as fp16 (direct into resident x-tile)
    #pragma unroll
    for (int mt = 0; mt < 2; mt++) {
        const int nl = mw * 32 + mt * 16 + (lane >> 2);
        const float i0 = s_den[nl], i1 = s_den[nl + 8];
        #pragma unroll
        for (int ct = 0; ct < 8; ct++) {
            const int c = cw * 64 + ct * 8 + (lane & 3) * 2;
            const float* a = acc[mt * 8 + ct];
            __half* r0 = (__half*)(smc + XOFF + (128 + c) * 144);
            __half* r1 = (__half*)(smc + XOFF + (129 + c) * 144);
            r0[nl]     = __float2half_rn(a[0] * i0);
            r1[nl]     = __float2half_rn(a[1] * i0);
            r0[nl + 8] = __float2half_rn(a[2] * i1);
            r1[nl + 8] = __float2half_rn(a[3] * i1);
        }
    }
    __syncthreads();   // x complete; interp workspace (incl. s_ds/s_den) dead

    // ================= Phase 2: MLP =================
    const int ow = w >> 1, nw = w & 1;   // GEMM1 warp: 64 o x 32 n

    // W1 chunk via cp.async of prequantized fp16: 4 x 16B per thread
    #define FILLW1(kc) do {                                                         \
        const int _buf = (kc) & 1;                                                  \
        _Pragma("unroll")                                                           \
        for (int it = 0; it < 4; it++) {                                            \
            const int u = tid + it * 256;                                           \
            const int o = u >> 2, s = u & 3;                                        \
            CP16(sb + MW(_buf) + PR(o) + s * 16,                                    \
                 g_w1f + (size_t)o * CINn + (kc) * 32 + s * 8);                     \
        }                                                                           \
        CPCOMMIT();                                                                 \
    } while (0)

    // W2 chunk via cp.async: 2 x 16B per thread
    #define FILLW2(kc) do {                                                         \
        const int _buf = (kc) & 1;                                                  \
        _Pragma("unroll")                                                           \
        for (int it = 0; it < 2; it++) {                                            \
            const int u = tid + it * 256;                                           \
            const int o = u >> 2, s = u & 3;                                        \
            CP16(sb + MW2(_buf) + PR(o) + s * 16,                                   \
                 g_w2f + (size_t)o * H1n + (kc) * 32 + s * 8);                      \
        }                                                                           \
        CPCOMMIT();                                                                 \
    } while (0)

    // reuse acc as acc1
    #pragma unroll
    for (int i = 0; i < 16; i++)
        #pragma unroll
        for (int j = 0; j < 4; j++) acc[i][j] = 0.f;

    FILLW1(0);

    for (int kc = 0; kc < 12; kc++) {
        const int buf = kc & 1;
        CPWAIT(0);
        __syncthreads();
        if (kc < 11) FILLW1(kc + 1);    // writes OTHER buffer — safe

        #pragma unroll
        for (int kk = 0; kk < 2; kk++) {
            uint32_t wh[4][4];
            #pragma unroll
            for (int mi = 0; mi < 4; mi++) {
                const uint32_t o = ow * 64 + mi * 16 + (lane & 15);
                const uint32_t off = PR(o) + kk * 32 + (lane >> 4) * 16;
                ldsm4(wh[mi], sb + MW(buf) + off);
            }
            uint32_t xh[4][2];
            #pragma unroll
            for (int np = 0; np < 2; np++) {
                const uint32_t row  = kc * 32 + kk * 16 + ((lane >> 3) & 1) * 8 + (lane & 7);
                const uint32_t colb = (nw * 32 + np * 16) * 2 + (lane >> 4) * 16;
                uint32_t r[4];
                ldsm4t(r, sb + XOFF + row * 144 + colb);
                xh[np * 2][0] = r[0]; xh[np * 2][1] = r[1];
                xh[np * 2 + 1][0] = r[2]; xh[np * 2 + 1][1] = r[3];
            }
            #pragma unroll
            for (int mi = 0; mi < 4; mi++)
                #pragma unroll
                for (int ni = 0; ni < 4; ni++)
                    mma_f16(acc[mi * 4 + ni], wh[mi], xh[ni]);
        }
    }
    #undef FILLW1

    __syncthreads();   // all warps done reading MW before h-epilogue overlays it
    FILLW2(0);

    // GEMM1 epilogue: relu + bias -> h [256 k-rows][64 n] fp16 (overlays MW)
    #pragma unroll
    for (int mi = 0; mi < 4; mi++) {
        const int o = ow * 64 + mi * 16 + (lane >> 2);
        const float bia0 = s_b1[o], bia1 = s_b1[o + 8];
        #pragma unroll
        for (int ni = 0; ni < 4; ni++) {
            const int n = nw * 32 + ni * 8 + (lane & 3) * 2;
            const float* a = acc[mi * 4 + ni];
            const float v0 = fmaxf(a[0] + bia0, 0.f);
            const float v1 = fmaxf(a[1] + bia0, 0.f);
            const float v2 = fmaxf(a[2] + bia1, 0.f);
            const float v3 = fmaxf(a[3] + bia1, 0.f);
            *(uint32_t*)(smc + MH + o * 144 + n * 2)       = h2pack(v0, v1);
            *(uint32_t*)(smc + MH + (o + 8) * 144 + n * 2) = h2pack(v2, v3);
        }
    }

    // GEMM2 (distance-1 double buffer)
    const int ow2 = w >> 1;
    float acc2[8][4];
    #pragma unroll
    for (int i = 0; i < 8; i++)
        #pragma unroll
        for (int j = 0; j < 4; j++) acc2[i][j] = 0.f;

    for (int kc = 0; kc < 8; kc++) {
        const int buf = kc & 1;
        CPWAIT(0);
        __syncthreads();            // first iter: h writes + FILLW2(0) visible
        if (kc < 7) FILLW2(kc + 1); // writes OTHER buffer — safe

        #pragma unroll
        for (int kk = 0; kk < 2; kk++) {
            uint32_t wh[2][4];
            #pragma unroll
            for (int mi = 0; mi < 2; mi++) {
                const uint32_t o = ow2 * 32 + mi * 16 + (lane & 15);
                const uint32_t off = PR(o) + kk * 32 + (lane >> 4) * 16;
                ldsm4(wh[mi], sb + MW2(buf) + off);
            }
            uint32_t hh[4][2];
            #pragma unroll
            for (int np = 0; np < 2; np++) {
                const uint32_t row  = kc * 32 + kk * 16 + ((lane >> 3) & 1) * 8 + (lane & 7);
                const uint32_t colb = (nw * 32 + np * 16) * 2 + (lane >> 4) * 16;
                uint32_t r[4];
                ldsm4t(r, sb + MH + row * 144 + colb);
                hh[np * 2][0] = r[0]; hh[np * 2][1] = r[1];
                hh[np * 2 + 1][0] = r[2]; hh[np * 2 + 1][1] = r[3];
            }
            #pragma unroll
            for (int mi = 0; mi < 2; mi++)
                #pragma unroll
                for (int ni = 0; ni < 4; ni++)
                    mma_f16(acc2[mi * 4 + ni], wh[mi], hh[ni]);
        }
    }
    #undef FILLW2

    // output
    #pragma unroll
    for (int mi = 0; mi < 2; mi++) {
        const int o = ow2 * 32 + mi * 16 + (lane >> 2);
        const float bia0 = s_b2[o], bia1 = s_b2[o + 8];
        #pragma unroll
        for (int ni = 0; ni < 4; ni++) {
            const int n = n0 + nw * 32 + ni * 8 + (lane & 3) * 2;
            const float* a = acc2[mi * 4 + ni];
            float2 v0, v1;
            v0.x = fmaxf(a[0] + bia0, 0.f);
            v0.y = fmaxf(a[1] + bia0, 0.f);
            v1.x = fmaxf(a[2] + bia1, 0.f);
            v1.y = fmaxf(a[3] + bia1, 0.f);
            *(float2*)&out[((size_t)b * H2n + o) * Nn + n]     = v0;
            *(float2*)&out[((size_t)b * H2n + o + 8) * Nn + n] = v1;
        }
    }
}

extern "C" void kernel_launch(void* const* d_in, const int* in_sizes, int n_in,
                              void* d_out, int out_size)
{
    const float* xyz1 = (const float*)d_in[0];
    const float* xyz2 = (const float*)d_in[1];
    const float* p1   = (const float*)d_in[2];
    const float* p2   = (const float*)d_in[3];
    const float* W1   = (const float*)d_in[4];
    const float* b1   = (const float*)d_in[5];
    const float* W2   = (const float*)d_in[6];
    const float* b2   = (const float*)d_in[7];
    float* out = (float*)d_out;

    cudaFuncSetAttribute(fp_fused, cudaFuncAttributeMaxDynamicSharedMemorySize, ISMB);

    prep_all<<<(int)PREP_BLKS, 256>>>(p2, p1, W1, W2);

    dim3 grid(Nn / 64, Bn);
    fp_fused<<<grid, 256, ISMB>>>(xyz1, xyz2, b1, b2, out);
}